// round 6
// baseline (speedup 1.0000x reference)
#include <cuda_runtime.h>

// Problem constants (fixed by the dataset)
#define T_TOK 16384
#define H_DIM 1024
#define E_NUM 16
#define F_DIM 2048
#define K_TOP 2
#define TK    (T_TOK * K_TOP)   // 32768 slots
#define N1    (2 * F_DIM)       // 4096 (gate/up interleaved)

#define BM 128
#define BN 128
#define BKs 8
#define MAX_TILES (TK / BM + E_NUM)   // 272 upper bound on sum ceil(cnt_e/128)

// -------- device scratch (allocation-free contract) --------
__device__ int   g_counts[E_NUM];
__device__ int   g_slots[E_NUM * TK];          // per-expert slot lists (2 MB)
__device__ int   g_numTiles;
__device__ int   g_tileE[MAX_TILES + 8];
__device__ int   g_tileRow[MAX_TILES + 8];
__device__ float g_inter[(size_t)TK * F_DIM];  // intermediate activations (256 MB)

// -------- 1) zero output + counters (must run every graph replay) --------
__global__ void k_init(float* __restrict__ out) {
    int i = blockIdx.x * blockDim.x + threadIdx.x;
    if (i < T_TOK * H_DIM) out[i] = 0.0f;
    if (i < E_NUM) g_counts[i] = 0;
}

// -------- 2) bucket slots per expert --------
__global__ void k_build(const int* __restrict__ topk_ids) {
    int i = blockIdx.x * blockDim.x + threadIdx.x;
    if (i < TK) {
        int e = topk_ids[i];
        int pos = atomicAdd(&g_counts[e], 1);
        g_slots[e * TK + pos] = i;   // slot = t*K + k
    }
}

// -------- 3) build compact (expert, rowTile) work list --------
__global__ void k_tilemap() {
    if (threadIdx.x == 0 && blockIdx.x == 0) {
        int idx = 0;
        for (int e = 0; e < E_NUM; e++) {
            int c = g_counts[e];
            for (int r = 0; r < c; r += BM) {
                g_tileE[idx] = e;
                g_tileRow[idx] = r;
                idx++;
            }
        }
        g_numTiles = idx;
    }
}

// -------- 4) grouped GEMM1: x @ W1[e] + b1, fused swiglu -> g_inter --------
__global__ __launch_bounds__(256) void k_gemm1(
    const float* __restrict__ hidden,   // [T, H]
    const float* __restrict__ W,        // [E, H, 2F]
    const float* __restrict__ bias)     // [E, 2F]
{
    int tileIdx = blockIdx.y;
    if (tileIdx >= g_numTiles) return;
    int e = g_tileE[tileIdx];
    int rowStart = g_tileRow[tileIdx];
    int rowsHere = min(BM, g_counts[e] - rowStart);
    int n0 = blockIdx.x * BN;

    __shared__ float As[BKs][BM];
    __shared__ float Bs[BKs][BN];
    __shared__ int   sTok[BM];
    __shared__ int   sSlot[BM];

    int tid = threadIdx.x;
    const int* slots = g_slots + e * TK + rowStart;
    if (tid < BM) {
        int slot = (tid < rowsHere) ? slots[tid] : 0;
        sSlot[tid] = slot;
        sTok[tid]  = slot / K_TOP;
    }
    __syncthreads();

    int aRow = tid >> 1;            // 0..127
    int aCol = (tid & 1) * 4;       // 0 or 4
    int bRow = tid >> 5;            // 0..7
    int bCol = (tid & 31) * 4;      // 0..124

    bool aValid = (aRow < rowsHere);
    const float* Aptr  = hidden + (size_t)sTok[aRow] * H_DIM + aCol;
    const float* Bbase = W + (size_t)e * H_DIM * N1 + n0 + bCol;

    int ty = tid >> 4, tx = tid & 15;
    float acc[8][8];
    #pragma unroll
    for (int i = 0; i < 8; i++)
        #pragma unroll
        for (int j = 0; j < 8; j++) acc[i][j] = 0.0f;

    for (int k0 = 0; k0 < H_DIM; k0 += BKs) {
        float4 av = aValid ? *(const float4*)(Aptr + k0) : make_float4(0.f, 0.f, 0.f, 0.f);
        float4 bv = *(const float4*)(Bbase + (size_t)(k0 + bRow) * N1);
        As[aCol + 0][aRow] = av.x; As[aCol + 1][aRow] = av.y;
        As[aCol + 2][aRow] = av.z; As[aCol + 3][aRow] = av.w;
        *(float4*)&Bs[bRow][bCol] = bv;
        __syncthreads();
        #pragma unroll
        for (int kk = 0; kk < BKs; kk++) {
            float a[8], b[8];
            #pragma unroll
            for (int i = 0; i < 8; i++) a[i] = As[kk][ty * 8 + i];
            #pragma unroll
            for (int j = 0; j < 8; j++) b[j] = Bs[kk][tx * 8 + j];
            #pragma unroll
            for (int i = 0; i < 8; i++)
                #pragma unroll
                for (int j = 0; j < 8; j++) acc[i][j] += a[i] * b[j];
        }
        __syncthreads();
    }

    // epilogue: bias + swiglu (pairs of interleaved cols), store to g_inter
    const float* bptr = bias + (size_t)e * N1 + n0 + tx * 8;
    #pragma unroll
    for (int i = 0; i < 8; i++) {
        int r = ty * 8 + i;
        if (r < rowsHere) {
            int slot = sSlot[r];
            float vals[4];
            #pragma unroll
            for (int p = 0; p < 4; p++) {
                float g = acc[i][2 * p]     + bptr[2 * p];
                float u = acc[i][2 * p + 1] + bptr[2 * p + 1];
                g = fminf(g, 7.0f);
                u = fminf(fmaxf(u, -7.0f), 7.0f);
                float glu = g / (1.0f + __expf(-1.702f * g));
                vals[p] = (u + 1.0f) * glu;
            }
            float* op = g_inter + (size_t)slot * F_DIM + (n0 >> 1) + tx * 4;
            *(float4*)op = make_float4(vals[0], vals[1], vals[2], vals[3]);
        }
    }
}

// -------- 5) grouped GEMM2: inter @ W2[e] + b2, weight + atomic combine --------
__global__ __launch_bounds__(256) void k_gemm2(
    const float* __restrict__ W,        // [E, F, H]
    const float* __restrict__ bias,     // [E, H]
    const float* __restrict__ tw,       // [T, K] flat -> index by slot
    float* __restrict__ out)            // [T, H]
{
    int tileIdx = blockIdx.y;
    if (tileIdx >= g_numTiles) return;
    int e = g_tileE[tileIdx];
    int rowStart = g_tileRow[tileIdx];
    int rowsHere = min(BM, g_counts[e] - rowStart);
    int n0 = blockIdx.x * BN;

    __shared__ float As[BKs][BM];
    __shared__ float Bs[BKs][BN];
    __shared__ int   sSlot[BM];
    __shared__ float sW[BM];

    int tid = threadIdx.x;
    const int* slots = g_slots + e * TK + rowStart;
    if (tid < BM) {
        int slot = (tid < rowsHere) ? slots[tid] : 0;
        sSlot[tid] = slot;
        sW[tid]    = tw[slot];
    }
    __syncthreads();

    int aRow = tid >> 1;
    int aCol = (tid & 1) * 4;
    int bRow = tid >> 5;
    int bCol = (tid & 31) * 4;

    bool aValid = (aRow < rowsHere);
    const float* Aptr  = g_inter + (size_t)sSlot[aRow] * F_DIM + aCol;
    const float* Bbase = W + (size_t)e * F_DIM * H_DIM + n0 + bCol;

    int ty = tid >> 4, tx = tid & 15;
    float acc[8][8];
    #pragma unroll
    for (int i = 0; i < 8; i++)
        #pragma unroll
        for (int j = 0; j < 8; j++) acc[i][j] = 0.0f;

    for (int k0 = 0; k0 < F_DIM; k0 += BKs) {
        float4 av = aValid ? *(const float4*)(Aptr + k0) : make_float4(0.f, 0.f, 0.f, 0.f);
        float4 bv = *(const float4*)(Bbase + (size_t)(k0 + bRow) * H_DIM);
        As[aCol + 0][aRow] = av.x; As[aCol + 1][aRow] = av.y;
        As[aCol + 2][aRow] = av.z; As[aCol + 3][aRow] = av.w;
        *(float4*)&Bs[bRow][bCol] = bv;
        __syncthreads();
        #pragma unroll
        for (int kk = 0; kk < BKs; kk++) {
            float a[8], b[8];
            #pragma unroll
            for (int i = 0; i < 8; i++) a[i] = As[kk][ty * 8 + i];
            #pragma unroll
            for (int j = 0; j < 8; j++) b[j] = Bs[kk][tx * 8 + j];
            #pragma unroll
            for (int i = 0; i < 8; i++)
                #pragma unroll
                for (int j = 0; j < 8; j++) acc[i][j] += a[i] * b[j];
        }
        __syncthreads();
    }

    // epilogue: bias, scale by routing weight, atomic combine into out[token]
    const float* bptr = bias + (size_t)e * H_DIM + n0 + tx * 8;
    #pragma unroll
    for (int i = 0; i < 8; i++) {
        int r = ty * 8 + i;
        if (r < rowsHere) {
            int slot = sSlot[r];
            float w = sW[r];
            int tok = slot / K_TOP;
            float* op = out + (size_t)tok * H_DIM + n0 + tx * 8;
            #pragma unroll
            for (int j = 0; j < 8; j++) {
                atomicAdd(op + j, w * (acc[i][j] + bptr[j]));
            }
        }
    }
}

extern "C" void kernel_launch(void* const* d_in, const int* in_sizes, int n_in,
                              void* d_out, int out_size) {
    const float* hidden = (const float*)d_in[0];   // [T, H]
    const float* tw     = (const float*)d_in[1];   // [T, K]
    const int*   ids    = (const int*)d_in[2];     // [T, K]
    const float* w1     = (const float*)d_in[3];   // [E, H, 2F]
    const float* b1     = (const float*)d_in[4];   // [E, 2F]
    const float* w2     = (const float*)d_in[5];   // [E, F, H]
    const float* b2     = (const float*)d_in[6];   // [E, H]
    float* out = (float*)d_out;                    // [T, H]

    int n = T_TOK * H_DIM;
    k_init<<<(n + 255) / 256, 256>>>(out);
    k_build<<<(TK + 255) / 256, 256>>>(ids);
    k_tilemap<<<1, 32>>>();
    k_gemm1<<<dim3(N1 / BN, MAX_TILES), 256>>>(hidden, w1, b1);
    k_gemm2<<<dim3(H_DIM / BN, MAX_TILES), 256>>>(w2, b2, tw, out);
}